// round 1
// baseline (speedup 1.0000x reference)
#include <cuda_runtime.h>
#include <math.h>

#define TOTAL_ATOMS 65536
#define NUM_GRAPHS  512
#define DMODEL      256
#define NHEAD       4
#define DHEAD       64
#define MAXN        192

// ---------------- scratch (static device globals; no allocation) ----------------
__device__ float g_qkv [ (size_t)TOTAL_ATOMS * 3 * DMODEL ];  // 192 MiB
__device__ float g_bufA[ (size_t)TOTAL_ATOMS * DMODEL ];      // 64 MiB (attn out)
__device__ float g_bufB[ (size_t)TOTAL_ATOMS * DMODEL ];      // 64 MiB (proj out)
__device__ float g_pooled[ NUM_GRAPHS * DMODEL ];
__device__ float g_r1    [ NUM_GRAPHS * DMODEL ];
__device__ float g_r2    [ NUM_GRAPHS * 128 ];
__device__ int   g_start [ NUM_GRAPHS + 1 ];

// ---------------- per-graph start offsets from sorted batch array ----------------
__global__ void compute_starts_kernel(const int* __restrict__ batch) {
    int i = blockIdx.x * blockDim.x + threadIdx.x;
    if (i >= TOTAL_ATOMS) return;
    if (i == 0) {
        g_start[batch[0]] = 0;
        g_start[NUM_GRAPHS] = TOTAL_ATOMS;
    } else if (batch[i] != batch[i - 1]) {
        g_start[batch[i]] = i;
    }
}

// ---------------- GEMM: C[m,n] = sum_k A[m,k]*B[n,k] + bias[n]  (A:MxK, B:NxK) ---
// BM=BN=128, BK=8, TM=TN=8, 256 threads. Requires M%128==0, N%128==0, K%8==0.
template <bool RELU>
__global__ void __launch_bounds__(256)
gemm_tn_kernel(const float* __restrict__ A, const float* __restrict__ B,
               const float* __restrict__ bias, float* __restrict__ C,
               int M, int N, int K) {
    const int BM = 128, BN = 128, BK = 8, TM = 8, TN = 8;
    __shared__ float As[BK][BM];
    __shared__ float Bs[BK][BN];

    int tid  = threadIdx.x;
    int brow = blockIdx.y;
    int bcol = blockIdx.x;

    const float* Ab = A + (size_t)brow * BM * K;
    const float* Bb = B + (size_t)bcol * BN * K;

    // load indices: one float4 per thread per tile
    int lr = tid >> 1;           // 0..127 row within tile
    int lc = (tid & 1) * 4;      // 0 or 4 within BK

    int ty = tid >> 4;           // 0..15
    int tx = tid & 15;           // 0..15

    float acc[TM][TN];
#pragma unroll
    for (int i = 0; i < TM; i++)
#pragma unroll
        for (int j = 0; j < TN; j++) acc[i][j] = 0.f;

    for (int k0 = 0; k0 < K; k0 += BK) {
        float4 a = *(const float4*)(Ab + (size_t)lr * K + k0 + lc);
        float4 b = *(const float4*)(Bb + (size_t)lr * K + k0 + lc);
        As[lc + 0][lr] = a.x; As[lc + 1][lr] = a.y;
        As[lc + 2][lr] = a.z; As[lc + 3][lr] = a.w;
        Bs[lc + 0][lr] = b.x; Bs[lc + 1][lr] = b.y;
        Bs[lc + 2][lr] = b.z; Bs[lc + 3][lr] = b.w;
        __syncthreads();

#pragma unroll
        for (int k = 0; k < BK; k++) {
            float ra[TM], rb[TN];
#pragma unroll
            for (int i = 0; i < TM; i++) ra[i] = As[k][ty * TM + i];
#pragma unroll
            for (int j = 0; j < TN; j++) rb[j] = Bs[k][tx * TN + j];
#pragma unroll
            for (int i = 0; i < TM; i++)
#pragma unroll
                for (int j = 0; j < TN; j++) acc[i][j] += ra[i] * rb[j];
        }
        __syncthreads();
    }

#pragma unroll
    for (int i = 0; i < TM; i++) {
        int row = brow * BM + ty * TM + i;
        float* crow = C + (size_t)row * N + bcol * BN + tx * TN;
#pragma unroll
        for (int j = 0; j < TN; j++) {
            float v = acc[i][j] + bias[bcol * BN + tx * TN + j];
            if (RELU) v = fmaxf(v, 0.f);
            crow[j] = v;
        }
    }
}

// ---------------- ragged per-(graph, head) attention ----------------
// qkv row layout: [q(256) | k(256) | v(256)]. One CTA per (graph, head).
// K/V staged in shared with stride 65 (bank-conflict-free row-per-lane reads).
// One warp per query row; warp-shuffle softmax.
__global__ void __launch_bounds__(256)
attention_kernel(const float* __restrict__ qkv, float* __restrict__ out) {
    extern __shared__ float sh[];
    float* Ks   = sh;                    // MAXN * 65
    float* Vs   = Ks + MAXN * 65;        // MAXN * 65
    float* sbuf = Vs + MAXN * 65;        // 8 * MAXN
    float* qbuf = sbuf + 8 * MAXN;       // 8 * 64

    int g = blockIdx.x;
    int h = blockIdx.y;
    int s0 = g_start[g];
    int n  = g_start[g + 1] - s0;

    int tid  = threadIdx.x;
    int lane = tid & 31;
    int warp = tid >> 5;

    // stage K and V for this (graph, head)
    for (int idx = tid; idx < n * DHEAD; idx += blockDim.x) {
        int r = idx >> 6;
        int d = idx & 63;
        const float* base = qkv + (size_t)(s0 + r) * (3 * DMODEL) + h * DHEAD + d;
        Ks[r * 65 + d] = base[DMODEL];       // k
        Vs[r * 65 + d] = base[2 * DMODEL];   // v
    }
    __syncthreads();

    const float scale = 0.125f;  // 1/sqrt(64)
    float* ss = sbuf + warp * MAXN;
    float* qb = qbuf + warp * 64;

    for (int r = warp; r < n; r += 8) {
        const float* qrow = qkv + (size_t)(s0 + r) * (3 * DMODEL) + h * DHEAD;
        qb[lane]      = qrow[lane];
        qb[lane + 32] = qrow[lane + 32];
        __syncwarp();

        // scores + running max
        float lmax = -1e30f;
        for (int k0 = 0; k0 < n; k0 += 32) {
            int kk = k0 + lane;
            if (kk < n) {
                const float* kr = Ks + kk * 65;
                float acc = 0.f;
#pragma unroll
                for (int d = 0; d < 64; d++) acc += qb[d] * kr[d];
                float s = acc * scale;
                ss[kk] = s;
                lmax = fmaxf(lmax, s);
            }
        }
#pragma unroll
        for (int o = 16; o; o >>= 1)
            lmax = fmaxf(lmax, __shfl_xor_sync(0xffffffffu, lmax, o));

        // exp + sum
        float lsum = 0.f;
        for (int kk = lane; kk < n; kk += 32) {
            float p = __expf(ss[kk] - lmax);
            ss[kk] = p;
            lsum += p;
        }
#pragma unroll
        for (int o = 16; o; o >>= 1)
            lsum += __shfl_xor_sync(0xffffffffu, lsum, o);
        float inv = 1.f / lsum;
        __syncwarp();  // ss[] fully written before cross-lane reads

        // o = P @ V  (each lane owns dims lane and lane+32)
        float o0 = 0.f, o1 = 0.f;
        for (int k = 0; k < n; k++) {
            float p = ss[k];
            o0 += p * Vs[k * 65 + lane];
            o1 += p * Vs[k * 65 + lane + 32];
        }
        float* orow = out + (size_t)(s0 + r) * DMODEL + h * DHEAD;
        orow[lane]      = o0 * inv;
        orow[lane + 32] = o1 * inv;
        __syncwarp();  // protect qb/ss reuse in next r iteration
    }
}

// ---------------- masked mean pool over each graph ----------------
__global__ void pool_kernel(const float* __restrict__ hin, float* __restrict__ pooled) {
    int g = blockIdx.x;
    int d = threadIdx.x;
    int s0 = g_start[g];
    int n  = g_start[g + 1] - s0;
    float s = 0.f;
    for (int r = 0; r < n; r++) s += hin[(size_t)(s0 + r) * DMODEL + d];
    pooled[g * DMODEL + d] = s / (float)n;
}

// ---------------- final 128 -> 1 dot ----------------
__global__ void final_kernel(const float* __restrict__ h2, const float* __restrict__ w,
                             const float* __restrict__ b, float* __restrict__ out) {
    __shared__ float red[128];
    int g = blockIdx.x;
    int t = threadIdx.x;
    red[t] = h2[g * 128 + t] * w[t];
    __syncthreads();
    for (int s = 64; s; s >>= 1) {
        if (t < s) red[t] += red[t + s];
        __syncthreads();
    }
    if (t == 0) out[g] = red[0] + b[0];
}

// ---------------- launch ----------------
extern "C" void kernel_launch(void* const* d_in, const int* in_sizes, int n_in,
                              void* d_out, int out_size) {
    const float* x      = (const float*)d_in[0];
    const int*   batch  = (const int*)  d_in[1];
    const float* in_w1  = (const float*)d_in[2];
    const float* in_b1  = (const float*)d_in[3];
    const float* out_w1 = (const float*)d_in[4];
    const float* out_b1 = (const float*)d_in[5];
    const float* in_w2  = (const float*)d_in[6];
    const float* in_b2  = (const float*)d_in[7];
    const float* out_w2 = (const float*)d_in[8];
    const float* out_b2 = (const float*)d_in[9];
    const float* r_w1   = (const float*)d_in[10];
    const float* r_b1   = (const float*)d_in[11];
    const float* r_w2   = (const float*)d_in[12];
    const float* r_b2   = (const float*)d_in[13];
    const float* r_w3   = (const float*)d_in[14];
    const float* r_b3   = (const float*)d_in[15];
    float* out = (float*)d_out;

    float *qkv, *bufA, *bufB, *pooled, *r1, *r2;
    cudaGetSymbolAddress((void**)&qkv,    g_qkv);
    cudaGetSymbolAddress((void**)&bufA,   g_bufA);
    cudaGetSymbolAddress((void**)&bufB,   g_bufB);
    cudaGetSymbolAddress((void**)&pooled, g_pooled);
    cudaGetSymbolAddress((void**)&r1,     g_r1);
    cudaGetSymbolAddress((void**)&r2,     g_r2);

    const int ATTN_SMEM = (MAXN * 65 * 2 + 8 * MAXN + 8 * 64) * (int)sizeof(float);
    cudaFuncSetAttribute(attention_kernel,
                         cudaFuncAttributeMaxDynamicSharedMemorySize, ATTN_SMEM);

    // graph offsets
    compute_starts_kernel<<<(TOTAL_ATOMS + 255) / 256, 256>>>(batch);

    dim3 gQKV(3 * DMODEL / 128, TOTAL_ATOMS / 128);
    dim3 gOUT(DMODEL / 128,     TOTAL_ATOMS / 128);
    dim3 gATT(NUM_GRAPHS, NHEAD);

    // layer 1
    gemm_tn_kernel<false><<<gQKV, 256>>>(x,    in_w1, in_b1, qkv, TOTAL_ATOMS, 3 * DMODEL, DMODEL);
    attention_kernel<<<gATT, 256, ATTN_SMEM>>>(qkv, bufA);
    gemm_tn_kernel<false><<<gOUT, 256>>>(bufA, out_w1, out_b1, bufB, TOTAL_ATOMS, DMODEL, DMODEL);

    // layer 2
    gemm_tn_kernel<false><<<gQKV, 256>>>(bufB, in_w2, in_b2, qkv, TOTAL_ATOMS, 3 * DMODEL, DMODEL);
    attention_kernel<<<gATT, 256, ATTN_SMEM>>>(qkv, bufA);
    gemm_tn_kernel<false><<<gOUT, 256>>>(bufA, out_w2, out_b2, bufB, TOTAL_ATOMS, DMODEL, DMODEL);

    // pool + readout MLP
    pool_kernel<<<NUM_GRAPHS, DMODEL>>>(bufB, pooled);

    dim3 gR1(DMODEL / 128, NUM_GRAPHS / 128);
    gemm_tn_kernel<true><<<gR1, 256>>>(pooled, r_w1, r_b1, r1, NUM_GRAPHS, DMODEL, DMODEL);
    dim3 gR2(128 / 128, NUM_GRAPHS / 128);
    gemm_tn_kernel<true><<<gR2, 256>>>(r1, r_w2, r_b2, r2, NUM_GRAPHS, 128, DMODEL);
    final_kernel<<<NUM_GRAPHS, 128>>>(r2, r_w3, r_b3, out);
}

// round 2
// speedup vs baseline: 1.3731x; 1.3731x over previous
#include <cuda_runtime.h>
#include <math.h>

#define TOTAL_ATOMS 65536
#define NUM_GRAPHS  512
#define DMODEL      256
#define NHEAD       4
#define DHEAD       64
#define NMAX        160   // actual graph sizes are in [96,160]

// ---------------- scratch (static device globals; no allocation) ----------------
__device__ float g_qkv [ (size_t)TOTAL_ATOMS * 3 * DMODEL ];
__device__ float g_bufA[ (size_t)TOTAL_ATOMS * DMODEL ];
__device__ float g_bufB[ (size_t)TOTAL_ATOMS * DMODEL ];
__device__ float g_pooled[ NUM_GRAPHS * DMODEL ];
__device__ float g_r1    [ NUM_GRAPHS * DMODEL ];
__device__ float g_r2    [ NUM_GRAPHS * 128 ];
__device__ int   g_start [ NUM_GRAPHS + 1 ];

// ---------------- per-graph start offsets ----------------
__global__ void compute_starts_kernel(const int* __restrict__ batch) {
    int i = blockIdx.x * blockDim.x + threadIdx.x;
    if (i >= TOTAL_ATOMS) return;
    if (i == 0) {
        g_start[batch[0]] = 0;
        g_start[NUM_GRAPHS] = TOTAL_ATOMS;
    } else if (batch[i] != batch[i - 1]) {
        g_start[batch[i]] = i;
    }
}

// ---------------- GEMM: C = A * B^T + bias. A:MxK, B:NxK. ----------------
// BM=BN=128, BK=8, 256 threads, bank-conflict-free split-fragment mapping.
template <bool RELU>
__global__ void __launch_bounds__(256)
gemm_tn_kernel(const float* __restrict__ A, const float* __restrict__ B,
               const float* __restrict__ bias, float* __restrict__ C,
               int M, int N, int K) {
    const int BM = 128, BN = 128, BK = 8;
    __shared__ float As[BK][BM];
    __shared__ float Bs[BK][BN];

    int tid  = threadIdx.x;
    int brow = blockIdx.y;
    int bcol = blockIdx.x;

    const float* Ab = A + (size_t)brow * BM * K;
    const float* Bb = B + (size_t)bcol * BN * K;

    int lr = tid >> 1;          // 0..127
    int lc = (tid & 1) * 4;     // 0 / 4

    int ty = tid >> 4;          // 0..15
    int tx = tid & 15;          // 0..15

    float acc[8][8];
#pragma unroll
    for (int i = 0; i < 8; i++)
#pragma unroll
        for (int j = 0; j < 8; j++) acc[i][j] = 0.f;

    for (int k0 = 0; k0 < K; k0 += BK) {
        float4 a = *(const float4*)(Ab + (size_t)lr * K + k0 + lc);
        float4 b = *(const float4*)(Bb + (size_t)lr * K + k0 + lc);
        As[lc + 0][lr] = a.x; As[lc + 1][lr] = a.y;
        As[lc + 2][lr] = a.z; As[lc + 3][lr] = a.w;
        Bs[lc + 0][lr] = b.x; Bs[lc + 1][lr] = b.y;
        Bs[lc + 2][lr] = b.z; Bs[lc + 3][lr] = b.w;
        __syncthreads();

#pragma unroll
        for (int k = 0; k < BK; k++) {
            // split fragments: rows {4ty..4ty+3, 64+4ty..}, cols {4tx..4tx+3, 64+4tx..}
            float4 a0 = *(const float4*)(&As[k][ty * 4]);
            float4 a1 = *(const float4*)(&As[k][64 + ty * 4]);
            float4 b0 = *(const float4*)(&Bs[k][tx * 4]);
            float4 b1 = *(const float4*)(&Bs[k][64 + tx * 4]);
            float ra[8] = {a0.x, a0.y, a0.z, a0.w, a1.x, a1.y, a1.z, a1.w};
            float rb[8] = {b0.x, b0.y, b0.z, b0.w, b1.x, b1.y, b1.z, b1.w};
#pragma unroll
            for (int i = 0; i < 8; i++)
#pragma unroll
                for (int j = 0; j < 8; j++) acc[i][j] += ra[i] * rb[j];
        }
        __syncthreads();
    }

    // bias (with same split-col mapping)
    float4 bb0 = *(const float4*)(bias + bcol * BN + tx * 4);
    float4 bb1 = *(const float4*)(bias + bcol * BN + 64 + tx * 4);
    float bv[8] = {bb0.x, bb0.y, bb0.z, bb0.w, bb1.x, bb1.y, bb1.z, bb1.w};

#pragma unroll
    for (int i = 0; i < 8; i++) {
        int row = brow * BM + (i < 4 ? ty * 4 + i : 64 + ty * 4 + (i - 4));
        float* crow = C + (size_t)row * N + bcol * BN;
        float4 c0, c1;
        float v[8];
#pragma unroll
        for (int j = 0; j < 8; j++) {
            float t = acc[i][j] + bv[j];
            if (RELU) t = fmaxf(t, 0.f);
            v[j] = t;
        }
        c0 = make_float4(v[0], v[1], v[2], v[3]);
        c1 = make_float4(v[4], v[5], v[6], v[7]);
        *(float4*)(crow + tx * 4)      = c0;
        *(float4*)(crow + 64 + tx * 4) = c1;
    }
}

// ---------------- ragged per-(graph, head) attention ----------------
// One CTA per (graph, head). K staged with XOR swizzle (float4 conflict-free for
// lane-varying rows), V unswizzled (float2, lane = dim pair). Two queries per
// warp pass to amortize K/V loads. smem ~96 KB -> 2 CTAs/SM.
__global__ void __launch_bounds__(256)
attention_kernel(const float* __restrict__ qkv, float* __restrict__ out) {
    extern __shared__ float sh[];
    float* Ks   = sh;                      // NMAX*64 (swizzled)
    float* Vs   = Ks + NMAX * 64;          // NMAX*64
    float* sbuf = Vs + NMAX * 64;          // 8 warps * 2 * NMAX
    float* qbuf = sbuf + 8 * 2 * NMAX;     // 8 warps * 128

    int g = blockIdx.x;
    int h = blockIdx.y;
    int s0 = g_start[g];
    int n  = g_start[g + 1] - s0;

    int tid  = threadIdx.x;
    int lane = tid & 31;
    int warp = tid >> 5;

    // ---- stage K (swizzled) and V (linear), float4 granularity ----
    float4* Ks4 = (float4*)Ks;
    float4* Vs4 = (float4*)Vs;
    for (int idx = tid; idx < n * 16; idx += 256) {
        int r  = idx >> 4;        // key row
        int dq = idx & 15;        // float4 column group
        const float* base = qkv + (size_t)(s0 + r) * (3 * DMODEL) + h * DHEAD;
        float4 kv = *(const float4*)(base + DMODEL     + dq * 4);
        float4 vv = *(const float4*)(base + 2 * DMODEL + dq * 4);
        Ks4[r * 16 + (dq ^ (r & 15))] = kv;
        Vs4[r * 16 + dq] = vv;
    }
    __syncthreads();

    const float scale = 0.125f;
    float* ss0 = sbuf + warp * 2 * NMAX;
    float* ss1 = ss0 + NMAX;
    float*  qb  = qbuf + warp * 128;
    float4* qb4a = (float4*)qb;
    float4* qb4b = (float4*)(qb + 64);
    float2* Vs2 = (float2*)Vs;

    for (int r0 = warp * 2; r0 < n; r0 += 16) {
        bool two = (r0 + 1 < n);
        int r1i = two ? r0 + 1 : r0;
        const float* q0 = qkv + (size_t)(s0 + r0)  * (3 * DMODEL) + h * DHEAD;
        const float* q1 = qkv + (size_t)(s0 + r1i) * (3 * DMODEL) + h * DHEAD;
        qb[lane]       = q0[lane];
        qb[lane + 32]  = q0[lane + 32];
        qb[64 + lane]      = q1[lane];
        qb[64 + lane + 32] = q1[lane + 32];
        __syncwarp();

        // ---- scores (lane = key) ----
        float m0 = -1e30f, m1 = -1e30f;
        for (int kc = 0; kc < n; kc += 32) {
            int kk = kc + lane;
            if (kk < n) {
                const float4* kr = Ks4 + kk * 16;
                int sw = kk & 15;
                float a0 = 0.f, a1 = 0.f;
#pragma unroll
                for (int dq = 0; dq < 16; dq++) {
                    float4 kv = kr[dq ^ sw];
                    float4 qa = qb4a[dq];
                    float4 qbv = qb4b[dq];
                    a0 += qa.x * kv.x + qa.y * kv.y + qa.z * kv.z + qa.w * kv.w;
                    a1 += qbv.x * kv.x + qbv.y * kv.y + qbv.z * kv.z + qbv.w * kv.w;
                }
                a0 *= scale; a1 *= scale;
                ss0[kk] = a0; ss1[kk] = a1;
                m0 = fmaxf(m0, a0); m1 = fmaxf(m1, a1);
            }
        }
#pragma unroll
        for (int o = 16; o; o >>= 1) {
            m0 = fmaxf(m0, __shfl_xor_sync(0xffffffffu, m0, o));
            m1 = fmaxf(m1, __shfl_xor_sync(0xffffffffu, m1, o));
        }

        // ---- exp + sum ----
        float t0 = 0.f, t1 = 0.f;
        for (int kk = lane; kk < n; kk += 32) {
            float p0 = __expf(ss0[kk] - m0);
            float p1 = __expf(ss1[kk] - m1);
            ss0[kk] = p0; ss1[kk] = p1;
            t0 += p0; t1 += p1;
        }
#pragma unroll
        for (int o = 16; o; o >>= 1) {
            t0 += __shfl_xor_sync(0xffffffffu, t0, o);
            t1 += __shfl_xor_sync(0xffffffffu, t1, o);
        }
        float inv0 = 1.f / t0, inv1 = 1.f / t1;
        __syncwarp();

        // ---- PV (lane = dim pair) ----
        float ox0 = 0.f, oy0 = 0.f, ox1 = 0.f, oy1 = 0.f;
#pragma unroll 4
        for (int k = 0; k < n; k++) {
            float2 v2 = Vs2[k * 32 + lane];
            float p0 = ss0[k];
            float p1 = ss1[k];
            ox0 += p0 * v2.x; oy0 += p0 * v2.y;
            ox1 += p1 * v2.x; oy1 += p1 * v2.y;
        }
        float2* o0p = (float2*)(out + (size_t)(s0 + r0) * DMODEL + h * DHEAD) + lane;
        *o0p = make_float2(ox0 * inv0, oy0 * inv0);
        if (two) {
            float2* o1p = (float2*)(out + (size_t)(s0 + r0 + 1) * DMODEL + h * DHEAD) + lane;
            *o1p = make_float2(ox1 * inv1, oy1 * inv1);
        }
        __syncwarp();
    }
}

// ---------------- masked mean pool ----------------
__global__ void pool_kernel(const float* __restrict__ hin, float* __restrict__ pooled) {
    int g = blockIdx.x;
    int d = threadIdx.x;
    int s0 = g_start[g];
    int n  = g_start[g + 1] - s0;
    float s = 0.f;
    for (int r = 0; r < n; r++) s += hin[(size_t)(s0 + r) * DMODEL + d];
    pooled[g * DMODEL + d] = s / (float)n;
}

// ---------------- final 128 -> 1 dot ----------------
__global__ void final_kernel(const float* __restrict__ h2, const float* __restrict__ w,
                             const float* __restrict__ b, float* __restrict__ out) {
    __shared__ float red[128];
    int g = blockIdx.x;
    int t = threadIdx.x;
    red[t] = h2[g * 128 + t] * w[t];
    __syncthreads();
    for (int s = 64; s; s >>= 1) {
        if (t < s) red[t] += red[t + s];
        __syncthreads();
    }
    if (t == 0) out[g] = red[0] + b[0];
}

// ---------------- launch ----------------
extern "C" void kernel_launch(void* const* d_in, const int* in_sizes, int n_in,
                              void* d_out, int out_size) {
    const float* x      = (const float*)d_in[0];
    const int*   batch  = (const int*)  d_in[1];
    const float* in_w1  = (const float*)d_in[2];
    const float* in_b1  = (const float*)d_in[3];
    const float* out_w1 = (const float*)d_in[4];
    const float* out_b1 = (const float*)d_in[5];
    const float* in_w2  = (const float*)d_in[6];
    const float* in_b2  = (const float*)d_in[7];
    const float* out_w2 = (const float*)d_in[8];
    const float* out_b2 = (const float*)d_in[9];
    const float* r_w1   = (const float*)d_in[10];
    const float* r_b1   = (const float*)d_in[11];
    const float* r_w2   = (const float*)d_in[12];
    const float* r_b2   = (const float*)d_in[13];
    const float* r_w3   = (const float*)d_in[14];
    const float* r_b3   = (const float*)d_in[15];
    float* out = (float*)d_out;

    float *qkv, *bufA, *bufB, *pooled, *r1, *r2;
    cudaGetSymbolAddress((void**)&qkv,    g_qkv);
    cudaGetSymbolAddress((void**)&bufA,   g_bufA);
    cudaGetSymbolAddress((void**)&bufB,   g_bufB);
    cudaGetSymbolAddress((void**)&pooled, g_pooled);
    cudaGetSymbolAddress((void**)&r1,     g_r1);
    cudaGetSymbolAddress((void**)&r2,     g_r2);

    const int ATTN_SMEM = (NMAX * 64 * 2 + 8 * 2 * NMAX + 8 * 128) * (int)sizeof(float);
    cudaFuncSetAttribute(attention_kernel,
                         cudaFuncAttributeMaxDynamicSharedMemorySize, ATTN_SMEM);

    compute_starts_kernel<<<(TOTAL_ATOMS + 255) / 256, 256>>>(batch);

    dim3 gQKV(3 * DMODEL / 128, TOTAL_ATOMS / 128);
    dim3 gOUT(DMODEL / 128,     TOTAL_ATOMS / 128);
    dim3 gATT(NUM_GRAPHS, NHEAD);

    // layer 1
    gemm_tn_kernel<false><<<gQKV, 256>>>(x,    in_w1, in_b1, qkv, TOTAL_ATOMS, 3 * DMODEL, DMODEL);
    attention_kernel<<<gATT, 256, ATTN_SMEM>>>(qkv, bufA);
    gemm_tn_kernel<false><<<gOUT, 256>>>(bufA, out_w1, out_b1, bufB, TOTAL_ATOMS, DMODEL, DMODEL);

    // layer 2
    gemm_tn_kernel<false><<<gQKV, 256>>>(bufB, in_w2, in_b2, qkv, TOTAL_ATOMS, 3 * DMODEL, DMODEL);
    attention_kernel<<<gATT, 256, ATTN_SMEM>>>(qkv, bufA);
    gemm_tn_kernel<false><<<gOUT, 256>>>(bufA, out_w2, out_b2, bufB, TOTAL_ATOMS, DMODEL, DMODEL);

    // pool + readout MLP
    pool_kernel<<<NUM_GRAPHS, DMODEL>>>(bufB, pooled);

    dim3 gR1(DMODEL / 128, NUM_GRAPHS / 128);
    gemm_tn_kernel<true><<<gR1, 256>>>(pooled, r_w1, r_b1, r1, NUM_GRAPHS, DMODEL, DMODEL);
    dim3 gR2(128 / 128, NUM_GRAPHS / 128);
    gemm_tn_kernel<true><<<gR2, 256>>>(r1, r_w2, r_b2, r2, NUM_GRAPHS, 128, DMODEL);
    final_kernel<<<NUM_GRAPHS, 128>>>(r2, r_w3, r_b3, out);
}

// round 4
// speedup vs baseline: 2.0967x; 1.5270x over previous
#include <cuda_runtime.h>
#include <cstdint>
#include <math.h>

#define TOTAL_ATOMS 65536
#define NUM_GRAPHS  512
#define DMODEL      256
#define NHEAD       4
#define DHEAD       64
#define NMAX        160   // actual graph sizes are in [96,160]

// ---------------- scratch ----------------
__device__ float g_qkv [ (size_t)TOTAL_ATOMS * 3 * DMODEL ];
__device__ float g_bufA[ (size_t)TOTAL_ATOMS * DMODEL ];
__device__ float g_bufB[ (size_t)TOTAL_ATOMS * DMODEL ];
__device__ float g_pooled[ NUM_GRAPHS * DMODEL ];
__device__ float g_r1    [ NUM_GRAPHS * DMODEL ];
__device__ float g_r2    [ NUM_GRAPHS * 128 ];
__device__ int   g_start [ NUM_GRAPHS + 1 ];

// ---------------- per-graph start offsets ----------------
__global__ void compute_starts_kernel(const int* __restrict__ batch) {
    int i = blockIdx.x * blockDim.x + threadIdx.x;
    if (i >= TOTAL_ATOMS) return;
    if (i == 0) {
        g_start[batch[0]] = 0;
        g_start[NUM_GRAPHS] = TOTAL_ATOMS;
    } else if (batch[i] != batch[i - 1]) {
        g_start[batch[i]] = i;
    }
}

// ================= tf32 mma.sync GEMM: C = A * B^T + bias =================
// A: [M,256], B: [Ntot,256] row-major, C: [M,Ntot]. K fixed = 256.
// CTA 128x128, BK=32, 8 warps (2M x 4N), warp tile 64x32 of m16n8k8 frags.

__device__ __forceinline__ uint32_t f2tf32(float x) {
    uint32_t u;
    asm("cvt.rna.tf32.f32 %0, %1;" : "=r"(u) : "f"(x));
    return u;
}

__device__ __forceinline__ void mma_tf32(float* d, const uint32_t* a, const uint32_t* b) {
    asm volatile(
        "mma.sync.aligned.m16n8k8.row.col.f32.tf32.tf32.f32 "
        "{%0,%1,%2,%3}, {%4,%5,%6,%7}, {%8,%9}, {%0,%1,%2,%3};"
        : "+f"(d[0]), "+f"(d[1]), "+f"(d[2]), "+f"(d[3])
        : "r"(a[0]), "r"(a[1]), "r"(a[2]), "r"(a[3]), "r"(b[0]), "r"(b[1]));
}

#define TCG_SMEM 65536  // 2 bufs x (A 16KB + B 16KB)

__global__ void __launch_bounds__(256)
mma_gemm_kernel(const float* __restrict__ A, const float* __restrict__ B,
                const float* __restrict__ bias, float* __restrict__ C, int Ntot) {
    extern __shared__ char smem[];
    const int K = DMODEL;  // 256

    int tid   = threadIdx.x;
    int lane  = tid & 31;
    int wid   = tid >> 5;
    int warpM = wid & 1;    // 0..1
    int warpN = wid >> 1;   // 0..3
    int m0 = blockIdx.y * 128;
    int n0 = blockIdx.x * 128;

    const float* Ab = A + (size_t)m0 * K;
    const float* Bb = B + (size_t)n0 * K;

    // staging indices: each thread stores 4 float4s per tile
    int srow = tid >> 3;        // 0..31 (+32*it)
    int sq   = tid & 7;         // float4 slot in 128B row

    float acc[4][4][4];
#pragma unroll
    for (int mt = 0; mt < 4; mt++)
#pragma unroll
        for (int nt = 0; nt < 4; nt++)
#pragma unroll
            for (int j = 0; j < 4; j++) acc[mt][nt][j] = 0.f;

    float4 ra[4], rb[4];
    // prefetch chunk 0
#pragma unroll
    for (int it = 0; it < 4; it++) {
        int row = srow + it * 32;
        ra[it] = *(const float4*)(Ab + (size_t)row * K + sq * 4);
        rb[it] = *(const float4*)(Bb + (size_t)row * K + sq * 4);
    }

    int r  = lane >> 2;
    int cc = lane & 3;

#pragma unroll 1
    for (int ch = 0; ch < 8; ch++) {
        int buf = ch & 1;
        char* As = smem + buf * 32768;
        char* Bs = As + 16384;

        // store staged regs with tf32 rounding, swizzled
#pragma unroll
        for (int it = 0; it < 4; it++) {
            int row = srow + it * 32;
            uint32_t off = row * 128 + ((sq ^ (row & 7)) << 4);
            uint4 va = make_uint4(f2tf32(ra[it].x), f2tf32(ra[it].y), f2tf32(ra[it].z), f2tf32(ra[it].w));
            uint4 vb = make_uint4(f2tf32(rb[it].x), f2tf32(rb[it].y), f2tf32(rb[it].z), f2tf32(rb[it].w));
            *(uint4*)(As + off) = va;
            *(uint4*)(Bs + off) = vb;
        }
        __syncthreads();

        // prefetch next chunk
        if (ch < 7) {
            int k0 = (ch + 1) * 32;
#pragma unroll
            for (int it = 0; it < 4; it++) {
                int row = srow + it * 32;
                ra[it] = *(const float4*)(Ab + (size_t)row * K + k0 + sq * 4);
                rb[it] = *(const float4*)(Bb + (size_t)row * K + k0 + sq * 4);
            }
        }

        // MMA over this buffer: 4 k-steps of 8
#pragma unroll
        for (int ks = 0; ks < 4; ks++) {
            uint32_t af[4][4];
#pragma unroll
            for (int mt = 0; mt < 4; mt++) {
                int row0 = warpM * 64 + mt * 16 + r;
                int sw = row0 & 7;  // (row0+8)&7 == sw
                uint32_t b0 = row0 * 128 + cc * 4;
                uint32_t b1 = (row0 + 8) * 128 + cc * 4;
                af[mt][0] = *(const uint32_t*)(As + b0 + (((ks * 2)     ^ sw) << 4));
                af[mt][1] = *(const uint32_t*)(As + b1 + (((ks * 2)     ^ sw) << 4));
                af[mt][2] = *(const uint32_t*)(As + b0 + (((ks * 2 + 1) ^ sw) << 4));
                af[mt][3] = *(const uint32_t*)(As + b1 + (((ks * 2 + 1) ^ sw) << 4));
            }
            uint32_t bf[4][2];
#pragma unroll
            for (int nt = 0; nt < 4; nt++) {
                int n = warpN * 32 + nt * 8 + r;
                int swn = n & 7;
                uint32_t bb = n * 128 + cc * 4;
                bf[nt][0] = *(const uint32_t*)(Bs + bb + (((ks * 2)     ^ swn) << 4));
                bf[nt][1] = *(const uint32_t*)(Bs + bb + (((ks * 2 + 1) ^ swn) << 4));
            }
#pragma unroll
            for (int mt = 0; mt < 4; mt++)
#pragma unroll
                for (int nt = 0; nt < 4; nt++)
                    mma_tf32(acc[mt][nt], af[mt], bf[nt]);
        }
        __syncthreads();
    }

    // epilogue: +bias, write C
    int c2 = (lane & 3) * 2;
#pragma unroll
    for (int nt = 0; nt < 4; nt++) {
        int col = n0 + warpN * 32 + nt * 8 + c2;
        float bx = bias[col], by = bias[col + 1];
#pragma unroll
        for (int mt = 0; mt < 4; mt++) {
            int row = m0 + warpM * 64 + mt * 16 + r;
            float* p0 = C + (size_t)row * Ntot + col;
            float* p1 = C + (size_t)(row + 8) * Ntot + col;
            *(float2*)p0 = make_float2(acc[mt][nt][0] + bx, acc[mt][nt][1] + by);
            *(float2*)p1 = make_float2(acc[mt][nt][2] + bx, acc[mt][nt][3] + by);
        }
    }
}

// ---------------- fp32 GEMM (small readout layers) ----------------
template <bool RELU>
__global__ void __launch_bounds__(256)
gemm_tn_kernel(const float* __restrict__ A, const float* __restrict__ B,
               const float* __restrict__ bias, float* __restrict__ C,
               int M, int N, int K) {
    const int BM = 128, BN = 128, BK = 8;
    __shared__ float As[BK][BM];
    __shared__ float Bs[BK][BN];

    int tid  = threadIdx.x;
    int brow = blockIdx.y;
    int bcol = blockIdx.x;

    const float* Ab = A + (size_t)brow * BM * K;
    const float* Bb = B + (size_t)bcol * BN * K;

    int lr = tid >> 1;
    int lc = (tid & 1) * 4;
    int ty = tid >> 4;
    int tx = tid & 15;

    float acc[8][8];
#pragma unroll
    for (int i = 0; i < 8; i++)
#pragma unroll
        for (int j = 0; j < 8; j++) acc[i][j] = 0.f;

    for (int k0 = 0; k0 < K; k0 += BK) {
        float4 a = *(const float4*)(Ab + (size_t)lr * K + k0 + lc);
        float4 b = *(const float4*)(Bb + (size_t)lr * K + k0 + lc);
        As[lc + 0][lr] = a.x; As[lc + 1][lr] = a.y;
        As[lc + 2][lr] = a.z; As[lc + 3][lr] = a.w;
        Bs[lc + 0][lr] = b.x; Bs[lc + 1][lr] = b.y;
        Bs[lc + 2][lr] = b.z; Bs[lc + 3][lr] = b.w;
        __syncthreads();
#pragma unroll
        for (int k = 0; k < BK; k++) {
            float4 a0 = *(const float4*)(&As[k][ty * 4]);
            float4 a1 = *(const float4*)(&As[k][64 + ty * 4]);
            float4 b0 = *(const float4*)(&Bs[k][tx * 4]);
            float4 b1 = *(const float4*)(&Bs[k][64 + tx * 4]);
            float ra[8] = {a0.x, a0.y, a0.z, a0.w, a1.x, a1.y, a1.z, a1.w};
            float rb[8] = {b0.x, b0.y, b0.z, b0.w, b1.x, b1.y, b1.z, b1.w};
#pragma unroll
            for (int i = 0; i < 8; i++)
#pragma unroll
                for (int j = 0; j < 8; j++) acc[i][j] += ra[i] * rb[j];
        }
        __syncthreads();
    }

    float4 bb0 = *(const float4*)(bias + bcol * BN + tx * 4);
    float4 bb1 = *(const float4*)(bias + bcol * BN + 64 + tx * 4);
    float bv[8] = {bb0.x, bb0.y, bb0.z, bb0.w, bb1.x, bb1.y, bb1.z, bb1.w};

#pragma unroll
    for (int i = 0; i < 8; i++) {
        int row = brow * BM + (i < 4 ? ty * 4 + i : 64 + ty * 4 + (i - 4));
        float* crow = C + (size_t)row * N + bcol * BN;
        float v[8];
#pragma unroll
        for (int j = 0; j < 8; j++) {
            float t = acc[i][j] + bv[j];
            if (RELU) t = fmaxf(t, 0.f);
            v[j] = t;
        }
        *(float4*)(crow + tx * 4)      = make_float4(v[0], v[1], v[2], v[3]);
        *(float4*)(crow + 64 + tx * 4) = make_float4(v[4], v[5], v[6], v[7]);
    }
}

// ---------------- ragged per-(graph, head) attention ----------------
__global__ void __launch_bounds__(256)
attention_kernel(const float* __restrict__ qkv, float* __restrict__ out) {
    extern __shared__ float sh[];
    float* Ks   = sh;
    float* Vs   = Ks + NMAX * 64;
    float* sbuf = Vs + NMAX * 64;
    float* qbuf = sbuf + 8 * 2 * NMAX;

    int g = blockIdx.x;
    int h = blockIdx.y;
    int s0 = g_start[g];
    int n  = g_start[g + 1] - s0;

    int tid  = threadIdx.x;
    int lane = tid & 31;
    int warp = tid >> 5;

    float4* Ks4 = (float4*)Ks;
    float4* Vs4 = (float4*)Vs;
    for (int idx = tid; idx < n * 16; idx += 256) {
        int r  = idx >> 4;
        int dq = idx & 15;
        const float* base = qkv + (size_t)(s0 + r) * (3 * DMODEL) + h * DHEAD;
        float4 kv = *(const float4*)(base + DMODEL     + dq * 4);
        float4 vv = *(const float4*)(base + 2 * DMODEL + dq * 4);
        Ks4[r * 16 + (dq ^ (r & 15))] = kv;
        Vs4[r * 16 + dq] = vv;
    }
    __syncthreads();

    const float scale = 0.125f;
    float* ss0 = sbuf + warp * 2 * NMAX;
    float* ss1 = ss0 + NMAX;
    float*  qb  = qbuf + warp * 128;
    float4* qb4a = (float4*)qb;
    float4* qb4b = (float4*)(qb + 64);
    float2* Vs2 = (float2*)Vs;

    for (int r0 = warp * 2; r0 < n; r0 += 16) {
        bool two = (r0 + 1 < n);
        int r1i = two ? r0 + 1 : r0;
        const float* q0 = qkv + (size_t)(s0 + r0)  * (3 * DMODEL) + h * DHEAD;
        const float* q1 = qkv + (size_t)(s0 + r1i) * (3 * DMODEL) + h * DHEAD;
        qb[lane]       = q0[lane];
        qb[lane + 32]  = q0[lane + 32];
        qb[64 + lane]      = q1[lane];
        qb[64 + lane + 32] = q1[lane + 32];
        __syncwarp();

        float m0 = -1e30f, m1 = -1e30f;
        for (int kc = 0; kc < n; kc += 32) {
            int kk = kc + lane;
            if (kk < n) {
                const float4* kr = Ks4 + kk * 16;
                int sw = kk & 15;
                float a0 = 0.f, a1 = 0.f;
#pragma unroll
                for (int dq = 0; dq < 16; dq++) {
                    float4 kv = kr[dq ^ sw];
                    float4 qa = qb4a[dq];
                    float4 qbv = qb4b[dq];
                    a0 += qa.x * kv.x + qa.y * kv.y + qa.z * kv.z + qa.w * kv.w;
                    a1 += qbv.x * kv.x + qbv.y * kv.y + qbv.z * kv.z + qbv.w * kv.w;
                }
                a0 *= scale; a1 *= scale;
                ss0[kk] = a0; ss1[kk] = a1;
                m0 = fmaxf(m0, a0); m1 = fmaxf(m1, a1);
            }
        }
#pragma unroll
        for (int o = 16; o; o >>= 1) {
            m0 = fmaxf(m0, __shfl_xor_sync(0xffffffffu, m0, o));
            m1 = fmaxf(m1, __shfl_xor_sync(0xffffffffu, m1, o));
        }

        float t0 = 0.f, t1 = 0.f;
        for (int kk = lane; kk < n; kk += 32) {
            float p0 = __expf(ss0[kk] - m0);
            float p1 = __expf(ss1[kk] - m1);
            ss0[kk] = p0; ss1[kk] = p1;
            t0 += p0; t1 += p1;
        }
#pragma unroll
        for (int o = 16; o; o >>= 1) {
            t0 += __shfl_xor_sync(0xffffffffu, t0, o);
            t1 += __shfl_xor_sync(0xffffffffu, t1, o);
        }
        float inv0 = 1.f / t0, inv1 = 1.f / t1;
        __syncwarp();

        float ox0 = 0.f, oy0 = 0.f, ox1 = 0.f, oy1 = 0.f;
#pragma unroll 4
        for (int k = 0; k < n; k++) {
            float2 v2 = Vs2[k * 32 + lane];
            float p0 = ss0[k];
            float p1 = ss1[k];
            ox0 += p0 * v2.x; oy0 += p0 * v2.y;
            ox1 += p1 * v2.x; oy1 += p1 * v2.y;
        }
        float2* o0p = (float2*)(out + (size_t)(s0 + r0) * DMODEL + h * DHEAD) + lane;
        *o0p = make_float2(ox0 * inv0, oy0 * inv0);
        if (two) {
            float2* o1p = (float2*)(out + (size_t)(s0 + r0 + 1) * DMODEL + h * DHEAD) + lane;
            *o1p = make_float2(ox1 * inv1, oy1 * inv1);
        }
        __syncwarp();
    }
}

// ---------------- masked mean pool ----------------
__global__ void pool_kernel(const float* __restrict__ hin, float* __restrict__ pooled) {
    int g = blockIdx.x;
    int d = threadIdx.x;
    int s0 = g_start[g];
    int n  = g_start[g + 1] - s0;
    float s = 0.f;
    for (int r = 0; r < n; r++) s += hin[(size_t)(s0 + r) * DMODEL + d];
    pooled[g * DMODEL + d] = s / (float)n;
}

// ---------------- final 128 -> 1 dot ----------------
__global__ void final_kernel(const float* __restrict__ h2, const float* __restrict__ w,
                             const float* __restrict__ b, float* __restrict__ out) {
    __shared__ float red[128];
    int g = blockIdx.x;
    int t = threadIdx.x;
    red[t] = h2[g * 128 + t] * w[t];
    __syncthreads();
    for (int s = 64; s; s >>= 1) {
        if (t < s) red[t] += red[t + s];
        __syncthreads();
    }
    if (t == 0) out[g] = red[0] + b[0];
}

// ---------------- launch ----------------
extern "C" void kernel_launch(void* const* d_in, const int* in_sizes, int n_in,
                              void* d_out, int out_size) {
    const float* x      = (const float*)d_in[0];
    const int*   batch  = (const int*)  d_in[1];
    const float* in_w1  = (const float*)d_in[2];
    const float* in_b1  = (const float*)d_in[3];
    const float* out_w1 = (const float*)d_in[4];
    const float* out_b1 = (const float*)d_in[5];
    const float* in_w2  = (const float*)d_in[6];
    const float* in_b2  = (const float*)d_in[7];
    const float* out_w2 = (const float*)d_in[8];
    const float* out_b2 = (const float*)d_in[9];
    const float* r_w1   = (const float*)d_in[10];
    const float* r_b1   = (const float*)d_in[11];
    const float* r_w2   = (const float*)d_in[12];
    const float* r_b2   = (const float*)d_in[13];
    const float* r_w3   = (const float*)d_in[14];
    const float* r_b3   = (const float*)d_in[15];
    float* out = (float*)d_out;

    float *qkv, *bufA, *bufB, *pooled, *r1, *r2;
    cudaGetSymbolAddress((void**)&qkv,    g_qkv);
    cudaGetSymbolAddress((void**)&bufA,   g_bufA);
    cudaGetSymbolAddress((void**)&bufB,   g_bufB);
    cudaGetSymbolAddress((void**)&pooled, g_pooled);
    cudaGetSymbolAddress((void**)&r1,     g_r1);
    cudaGetSymbolAddress((void**)&r2,     g_r2);

    const int ATTN_SMEM = (NMAX * 64 * 2 + 8 * 2 * NMAX + 8 * 128) * (int)sizeof(float);
    cudaFuncSetAttribute(attention_kernel,
                         cudaFuncAttributeMaxDynamicSharedMemorySize, ATTN_SMEM);
    cudaFuncSetAttribute(mma_gemm_kernel,
                         cudaFuncAttributeMaxDynamicSharedMemorySize, TCG_SMEM);

    compute_starts_kernel<<<(TOTAL_ATOMS + 255) / 256, 256>>>(batch);

    dim3 gQKV(3 * DMODEL / 128, TOTAL_ATOMS / 128);   // 6 x 512
    dim3 gOUT(DMODEL / 128,     TOTAL_ATOMS / 128);   // 2 x 512
    dim3 gATT(NUM_GRAPHS, NHEAD);

    // layer 1
    mma_gemm_kernel<<<gQKV, 256, TCG_SMEM>>>(x,    in_w1,  in_b1,  qkv,  3 * DMODEL);
    attention_kernel<<<gATT, 256, ATTN_SMEM>>>(qkv, bufA);
    mma_gemm_kernel<<<gOUT, 256, TCG_SMEM>>>(bufA, out_w1, out_b1, bufB, DMODEL);

    // layer 2
    mma_gemm_kernel<<<gQKV, 256, TCG_SMEM>>>(bufB, in_w2,  in_b2,  qkv,  3 * DMODEL);
    attention_kernel<<<gATT, 256, ATTN_SMEM>>>(qkv, bufA);
    mma_gemm_kernel<<<gOUT, 256, TCG_SMEM>>>(bufA, out_w2, out_b2, bufB, DMODEL);

    // pool + readout MLP
    pool_kernel<<<NUM_GRAPHS, DMODEL>>>(bufB, pooled);

    dim3 gR1(DMODEL / 128, NUM_GRAPHS / 128);
    gemm_tn_kernel<true><<<gR1, 256>>>(pooled, r_w1, r_b1, r1, NUM_GRAPHS, DMODEL, DMODEL);
    dim3 gR2(1, NUM_GRAPHS / 128);
    gemm_tn_kernel<true><<<gR2, 256>>>(r1, r_w2, r_b2, r2, NUM_GRAPHS, 128, DMODEL);
    final_kernel<<<NUM_GRAPHS, 128>>>(r2, r_w3, r_b3, out);
}

// round 5
// speedup vs baseline: 3.0189x; 1.4399x over previous
#include <cuda_runtime.h>
#include <cstdint>
#include <math.h>

#define TOTAL_ATOMS 65536
#define NUM_GRAPHS  512
#define DMODEL      256
#define NHEAD       4
#define DHEAD       64
#define NMAX        160   // actual graph sizes are in [96,160]

// ---------------- scratch ----------------
__device__ float g_qkv [ (size_t)TOTAL_ATOMS * 3 * DMODEL ];
__device__ float g_bufA[ (size_t)TOTAL_ATOMS * DMODEL ];
__device__ float g_bufB[ (size_t)TOTAL_ATOMS * DMODEL ];
__device__ float g_pooled[ NUM_GRAPHS * DMODEL ];
__device__ float g_r1    [ NUM_GRAPHS * DMODEL ];
__device__ float g_r2    [ NUM_GRAPHS * 128 ];
__device__ int   g_start [ NUM_GRAPHS + 1 ];

// ---------------- per-graph start offsets ----------------
__global__ void compute_starts_kernel(const int* __restrict__ batch) {
    int i = blockIdx.x * blockDim.x + threadIdx.x;
    if (i >= TOTAL_ATOMS) return;
    if (i == 0) {
        g_start[batch[0]] = 0;
        g_start[NUM_GRAPHS] = TOTAL_ATOMS;
    } else if (batch[i] != batch[i - 1]) {
        g_start[batch[i]] = i;
    }
}

// ---------------- tf32 helpers ----------------
__device__ __forceinline__ uint32_t f2tf32(float x) {
    uint32_t u;
    asm("cvt.rna.tf32.f32 %0, %1;" : "=r"(u) : "f"(x));
    return u;
}
__device__ __forceinline__ void mma_tf32(float* d, const uint32_t* a, const uint32_t* b) {
    asm volatile(
        "mma.sync.aligned.m16n8k8.row.col.f32.tf32.tf32.f32 "
        "{%0,%1,%2,%3}, {%4,%5,%6,%7}, {%8,%9}, {%0,%1,%2,%3};"
        : "+f"(d[0]), "+f"(d[1]), "+f"(d[2]), "+f"(d[3])
        : "r"(a[0]), "r"(a[1]), "r"(a[2]), "r"(a[3]), "r"(b[0]), "r"(b[1]));
}

// ================= tf32 mma.sync GEMM: C = A * B^T + bias =================
#define TCG_SMEM 65536

__global__ void __launch_bounds__(256)
mma_gemm_kernel(const float* __restrict__ A, const float* __restrict__ B,
                const float* __restrict__ bias, float* __restrict__ C, int Ntot) {
    extern __shared__ char smem[];
    const int K = DMODEL;

    int tid   = threadIdx.x;
    int lane  = tid & 31;
    int wid   = tid >> 5;
    int warpM = wid & 1;
    int warpN = wid >> 1;
    int m0 = blockIdx.y * 128;
    int n0 = blockIdx.x * 128;

    const float* Ab = A + (size_t)m0 * K;
    const float* Bb = B + (size_t)n0 * K;

    int srow = tid >> 3;
    int sq   = tid & 7;

    float acc[4][4][4];
#pragma unroll
    for (int mt = 0; mt < 4; mt++)
#pragma unroll
        for (int nt = 0; nt < 4; nt++)
#pragma unroll
            for (int j = 0; j < 4; j++) acc[mt][nt][j] = 0.f;

    float4 ra[4], rb[4];
#pragma unroll
    for (int it = 0; it < 4; it++) {
        int row = srow + it * 32;
        ra[it] = *(const float4*)(Ab + (size_t)row * K + sq * 4);
        rb[it] = *(const float4*)(Bb + (size_t)row * K + sq * 4);
    }

    int r  = lane >> 2;
    int cc = lane & 3;

#pragma unroll 1
    for (int ch = 0; ch < 8; ch++) {
        int buf = ch & 1;
        char* As = smem + buf * 32768;
        char* Bs = As + 16384;

#pragma unroll
        for (int it = 0; it < 4; it++) {
            int row = srow + it * 32;
            uint32_t off = row * 128 + ((sq ^ (row & 7)) << 4);
            uint4 va = make_uint4(f2tf32(ra[it].x), f2tf32(ra[it].y), f2tf32(ra[it].z), f2tf32(ra[it].w));
            uint4 vb = make_uint4(f2tf32(rb[it].x), f2tf32(rb[it].y), f2tf32(rb[it].z), f2tf32(rb[it].w));
            *(uint4*)(As + off) = va;
            *(uint4*)(Bs + off) = vb;
        }
        __syncthreads();

        if (ch < 7) {
            int k0 = (ch + 1) * 32;
#pragma unroll
            for (int it = 0; it < 4; it++) {
                int row = srow + it * 32;
                ra[it] = *(const float4*)(Ab + (size_t)row * K + k0 + sq * 4);
                rb[it] = *(const float4*)(Bb + (size_t)row * K + k0 + sq * 4);
            }
        }

#pragma unroll
        for (int ks = 0; ks < 4; ks++) {
            uint32_t af[4][4];
#pragma unroll
            for (int mt = 0; mt < 4; mt++) {
                int row0 = warpM * 64 + mt * 16 + r;
                int sw = row0 & 7;
                uint32_t b0 = row0 * 128 + cc * 4;
                uint32_t b1 = (row0 + 8) * 128 + cc * 4;
                af[mt][0] = *(const uint32_t*)(As + b0 + (((ks * 2)     ^ sw) << 4));
                af[mt][1] = *(const uint32_t*)(As + b1 + (((ks * 2)     ^ sw) << 4));
                af[mt][2] = *(const uint32_t*)(As + b0 + (((ks * 2 + 1) ^ sw) << 4));
                af[mt][3] = *(const uint32_t*)(As + b1 + (((ks * 2 + 1) ^ sw) << 4));
            }
            uint32_t bf[4][2];
#pragma unroll
            for (int nt = 0; nt < 4; nt++) {
                int n = warpN * 32 + nt * 8 + r;
                int swn = n & 7;
                uint32_t bb = n * 128 + cc * 4;
                bf[nt][0] = *(const uint32_t*)(Bs + bb + (((ks * 2)     ^ swn) << 4));
                bf[nt][1] = *(const uint32_t*)(Bs + bb + (((ks * 2 + 1) ^ swn) << 4));
            }
#pragma unroll
            for (int mt = 0; mt < 4; mt++)
#pragma unroll
                for (int nt = 0; nt < 4; nt++)
                    mma_tf32(acc[mt][nt], af[mt], bf[nt]);
        }
        __syncthreads();
    }

    int c2 = (lane & 3) * 2;
#pragma unroll
    for (int nt = 0; nt < 4; nt++) {
        int col = n0 + warpN * 32 + nt * 8 + c2;
        float bx = bias[col], by = bias[col + 1];
#pragma unroll
        for (int mt = 0; mt < 4; mt++) {
            int row = m0 + warpM * 64 + mt * 16 + r;
            float* p0 = C + (size_t)row * Ntot + col;
            float* p1 = C + (size_t)(row + 8) * Ntot + col;
            *(float2*)p0 = make_float2(acc[mt][nt][0] + bx, acc[mt][nt][1] + by);
            *(float2*)p1 = make_float2(acc[mt][nt][2] + bx, acc[mt][nt][3] + by);
        }
    }
}

// ---------------- fp32 GEMM (small readout layers) ----------------
template <bool RELU>
__global__ void __launch_bounds__(256)
gemm_tn_kernel(const float* __restrict__ A, const float* __restrict__ B,
               const float* __restrict__ bias, float* __restrict__ C,
               int M, int N, int K) {
    const int BM = 128, BN = 128, BK = 8;
    __shared__ float As[BK][BM];
    __shared__ float Bs[BK][BN];

    int tid  = threadIdx.x;
    int brow = blockIdx.y;
    int bcol = blockIdx.x;

    const float* Ab = A + (size_t)brow * BM * K;
    const float* Bb = B + (size_t)bcol * BN * K;

    int lr = tid >> 1;
    int lc = (tid & 1) * 4;
    int ty = tid >> 4;
    int tx = tid & 15;

    float acc[8][8];
#pragma unroll
    for (int i = 0; i < 8; i++)
#pragma unroll
        for (int j = 0; j < 8; j++) acc[i][j] = 0.f;

    for (int k0 = 0; k0 < K; k0 += BK) {
        float4 a = *(const float4*)(Ab + (size_t)lr * K + k0 + lc);
        float4 b = *(const float4*)(Bb + (size_t)lr * K + k0 + lc);
        As[lc + 0][lr] = a.x; As[lc + 1][lr] = a.y;
        As[lc + 2][lr] = a.z; As[lc + 3][lr] = a.w;
        Bs[lc + 0][lr] = b.x; Bs[lc + 1][lr] = b.y;
        Bs[lc + 2][lr] = b.z; Bs[lc + 3][lr] = b.w;
        __syncthreads();
#pragma unroll
        for (int k = 0; k < BK; k++) {
            float4 a0 = *(const float4*)(&As[k][ty * 4]);
            float4 a1 = *(const float4*)(&As[k][64 + ty * 4]);
            float4 b0 = *(const float4*)(&Bs[k][tx * 4]);
            float4 b1 = *(const float4*)(&Bs[k][64 + tx * 4]);
            float ra[8] = {a0.x, a0.y, a0.z, a0.w, a1.x, a1.y, a1.z, a1.w};
            float rb[8] = {b0.x, b0.y, b0.z, b0.w, b1.x, b1.y, b1.z, b1.w};
#pragma unroll
            for (int i = 0; i < 8; i++)
#pragma unroll
                for (int j = 0; j < 8; j++) acc[i][j] += ra[i] * rb[j];
        }
        __syncthreads();
    }

    float4 bb0 = *(const float4*)(bias + bcol * BN + tx * 4);
    float4 bb1 = *(const float4*)(bias + bcol * BN + 64 + tx * 4);
    float bv[8] = {bb0.x, bb0.y, bb0.z, bb0.w, bb1.x, bb1.y, bb1.z, bb1.w};

#pragma unroll
    for (int i = 0; i < 8; i++) {
        int row = brow * BM + (i < 4 ? ty * 4 + i : 64 + ty * 4 + (i - 4));
        float* crow = C + (size_t)row * N + bcol * BN;
        float v[8];
#pragma unroll
        for (int j = 0; j < 8; j++) {
            float t = acc[i][j] + bv[j];
            if (RELU) t = fmaxf(t, 0.f);
            v[j] = t;
        }
        *(float4*)(crow + tx * 4)      = make_float4(v[0], v[1], v[2], v[3]);
        *(float4*)(crow + 64 + tx * 4) = make_float4(v[4], v[5], v[6], v[7]);
    }
}

// ================= tensor-core attention (tf32 mma.sync) =================
// One CTA per (graph, head). Q/K/V staged tf32 in SMEM, stride 72 words
// (conflict-free for all fragment patterns). 8 warps, each owns 16-query
// m-tiles. S in registers (20 n-frags), register softmax, P via per-warp
// SMEM (stride 164), PV mma, normalize at store.
#define QS_STRIDE 72
#define PS_STRIDE 164
#define ATTN_SMEM3 ((3 * NMAX * QS_STRIDE + 8 * 16 * PS_STRIDE) * 4)

__global__ void __launch_bounds__(256)
attention_tc_kernel(const float* __restrict__ qkv, float* __restrict__ out) {
    extern __shared__ char sm[];
    uint32_t* Qs = (uint32_t*)sm;
    uint32_t* Ks = Qs + NMAX * QS_STRIDE;
    uint32_t* Vs = Ks + NMAX * QS_STRIDE;
    uint32_t* Ps = Vs + NMAX * QS_STRIDE;   // 8 warps * 16 * PS_STRIDE

    int g = blockIdx.x;
    int h = blockIdx.y;
    int s0 = g_start[g];
    int n  = g_start[g + 1] - s0;

    int tid  = threadIdx.x;
    int lane = tid & 31;
    int warp = tid >> 5;

    // ---- stage Q/K/V (tf32), zero-fill pad rows ----
    for (int idx = tid; idx < NMAX * 16; idx += 256) {
        int r = idx >> 4, q = idx & 15;
        uint4 qv = make_uint4(0, 0, 0, 0), kv = qv, vv = qv;
        if (r < n) {
            const float* base = qkv + (size_t)(s0 + r) * (3 * DMODEL) + h * DHEAD + q * 4;
            float4 a = *(const float4*)(base);
            float4 b = *(const float4*)(base + DMODEL);
            float4 c = *(const float4*)(base + 2 * DMODEL);
            qv = make_uint4(f2tf32(a.x), f2tf32(a.y), f2tf32(a.z), f2tf32(a.w));
            kv = make_uint4(f2tf32(b.x), f2tf32(b.y), f2tf32(b.z), f2tf32(b.w));
            vv = make_uint4(f2tf32(c.x), f2tf32(c.y), f2tf32(c.z), f2tf32(c.w));
        }
        *(uint4*)(Qs + r * QS_STRIDE + q * 4) = qv;
        *(uint4*)(Ks + r * QS_STRIDE + q * 4) = kv;
        *(uint4*)(Vs + r * QS_STRIDE + q * 4) = vv;
    }
    __syncthreads();

    int ntiles = (n + 15) >> 4;
    int nfc    = (n + 7) >> 3;
    int r = lane >> 2;
    int c = lane & 3;
    uint32_t* Pw = Ps + warp * 16 * PS_STRIDE;

#pragma unroll 1
    for (int mt = warp; mt < ntiles; mt += 8) {
        int m0 = mt * 16;

        // Q A-frags for all 8 k-steps
        uint32_t aq[8][4];
#pragma unroll
        for (int ks = 0; ks < 8; ks++) {
            const uint32_t* q0 = Qs + (m0 + r) * QS_STRIDE + ks * 8 + c;
            const uint32_t* q1 = Qs + (m0 + r + 8) * QS_STRIDE + ks * 8 + c;
            aq[ks][0] = q0[0];
            aq[ks][1] = q1[0];
            aq[ks][2] = q0[4];
            aq[ks][3] = q1[4];
        }

        // ---- S = Q K^T ----
        float s[20][4];
#pragma unroll
        for (int nf = 0; nf < 20; nf++) {
            s[nf][0] = 0.f; s[nf][1] = 0.f; s[nf][2] = 0.f; s[nf][3] = 0.f;
        }
#pragma unroll
        for (int nf = 0; nf < 20; nf++) {
            if (nf >= nfc) continue;
            const uint32_t* kb = Ks + (nf * 8 + r) * QS_STRIDE + c;
#pragma unroll
            for (int ks = 0; ks < 8; ks++) {
                uint32_t bf[2];
                bf[0] = kb[ks * 8];
                bf[1] = kb[ks * 8 + 4];
                mma_tf32(s[nf], aq[ks], bf);
            }
        }

        // ---- mask + scale ----
#pragma unroll
        for (int nf = 0; nf < 20; nf++) {
            int col0 = nf * 8 + 2 * c;
            s[nf][0] = (col0     < n) ? s[nf][0] * 0.125f : -1e30f;
            s[nf][1] = (col0 + 1 < n) ? s[nf][1] * 0.125f : -1e30f;
            s[nf][2] = (col0     < n) ? s[nf][2] * 0.125f : -1e30f;
            s[nf][3] = (col0 + 1 < n) ? s[nf][3] * 0.125f : -1e30f;
        }

        // ---- row max (rows r and r+8) ----
        float mx0 = -1e30f, mx1 = -1e30f;
#pragma unroll
        for (int nf = 0; nf < 20; nf++) {
            mx0 = fmaxf(mx0, fmaxf(s[nf][0], s[nf][1]));
            mx1 = fmaxf(mx1, fmaxf(s[nf][2], s[nf][3]));
        }
        mx0 = fmaxf(mx0, __shfl_xor_sync(0xffffffffu, mx0, 1));
        mx0 = fmaxf(mx0, __shfl_xor_sync(0xffffffffu, mx0, 2));
        mx1 = fmaxf(mx1, __shfl_xor_sync(0xffffffffu, mx1, 1));
        mx1 = fmaxf(mx1, __shfl_xor_sync(0xffffffffu, mx1, 2));

        // ---- exp + row sum ----
        float sum0 = 0.f, sum1 = 0.f;
#pragma unroll
        for (int nf = 0; nf < 20; nf++) {
            if (nf >= nfc) continue;
            float p0 = __expf(s[nf][0] - mx0);
            float p1 = __expf(s[nf][1] - mx0);
            float p2 = __expf(s[nf][2] - mx1);
            float p3 = __expf(s[nf][3] - mx1);
            s[nf][0] = p0; s[nf][1] = p1; s[nf][2] = p2; s[nf][3] = p3;
            sum0 += p0 + p1;
            sum1 += p2 + p3;
        }
        sum0 += __shfl_xor_sync(0xffffffffu, sum0, 1);
        sum0 += __shfl_xor_sync(0xffffffffu, sum0, 2);
        sum1 += __shfl_xor_sync(0xffffffffu, sum1, 1);
        sum1 += __shfl_xor_sync(0xffffffffu, sum1, 2);
        float inv0 = 1.f / sum0;
        float inv1 = 1.f / sum1;

        // ---- P -> smem (tf32, unnormalized) ----
        __syncwarp();
#pragma unroll
        for (int nf = 0; nf < 20; nf++) {
            if (nf >= nfc) continue;
            int col = nf * 8 + 2 * c;
            Pw[r * PS_STRIDE + col]           = f2tf32(s[nf][0]);
            Pw[r * PS_STRIDE + col + 1]       = f2tf32(s[nf][1]);
            Pw[(r + 8) * PS_STRIDE + col]     = f2tf32(s[nf][2]);
            Pw[(r + 8) * PS_STRIDE + col + 1] = f2tf32(s[nf][3]);
        }
        __syncwarp();

        // ---- O = P V ----
        float o[8][4];
#pragma unroll
        for (int nd = 0; nd < 8; nd++) {
            o[nd][0] = 0.f; o[nd][1] = 0.f; o[nd][2] = 0.f; o[nd][3] = 0.f;
        }
#pragma unroll
        for (int ks = 0; ks < 20; ks++) {
            if (ks >= nfc) continue;
            uint32_t ap[4];
            ap[0] = Pw[r * PS_STRIDE + ks * 8 + c];
            ap[1] = Pw[(r + 8) * PS_STRIDE + ks * 8 + c];
            ap[2] = Pw[r * PS_STRIDE + ks * 8 + c + 4];
            ap[3] = Pw[(r + 8) * PS_STRIDE + ks * 8 + c + 4];
            const uint32_t* vb0 = Vs + (ks * 8 + c) * QS_STRIDE + r;
            const uint32_t* vb1 = Vs + (ks * 8 + c + 4) * QS_STRIDE + r;
#pragma unroll
            for (int nd = 0; nd < 8; nd++) {
                uint32_t bf[2];
                bf[0] = vb0[nd * 8];
                bf[1] = vb1[nd * 8];
                mma_tf32(o[nd], ap, bf);
            }
        }

        // ---- normalize + write ----
        int row0 = m0 + r, row1 = m0 + r + 8;
#pragma unroll
        for (int nd = 0; nd < 8; nd++) {
            int col = h * DHEAD + nd * 8 + 2 * c;
            if (row0 < n)
                *(float2*)(out + (size_t)(s0 + row0) * DMODEL + col) =
                    make_float2(o[nd][0] * inv0, o[nd][1] * inv0);
            if (row1 < n)
                *(float2*)(out + (size_t)(s0 + row1) * DMODEL + col) =
                    make_float2(o[nd][2] * inv1, o[nd][3] * inv1);
        }
        __syncwarp();
    }
}

// ---------------- masked mean pool ----------------
__global__ void pool_kernel(const float* __restrict__ hin, float* __restrict__ pooled) {
    int g = blockIdx.x;
    int d = threadIdx.x;
    int s0 = g_start[g];
    int n  = g_start[g + 1] - s0;
    float s = 0.f;
    for (int r = 0; r < n; r++) s += hin[(size_t)(s0 + r) * DMODEL + d];
    pooled[g * DMODEL + d] = s / (float)n;
}

// ---------------- final 128 -> 1 dot ----------------
__global__ void final_kernel(const float* __restrict__ h2, const float* __restrict__ w,
                             const float* __restrict__ b, float* __restrict__ out) {
    __shared__ float red[128];
    int g = blockIdx.x;
    int t = threadIdx.x;
    red[t] = h2[g * 128 + t] * w[t];
    __syncthreads();
    for (int s = 64; s; s >>= 1) {
        if (t < s) red[t] += red[t + s];
        __syncthreads();
    }
    if (t == 0) out[g] = red[0] + b[0];
}

// ---------------- launch ----------------
extern "C" void kernel_launch(void* const* d_in, const int* in_sizes, int n_in,
                              void* d_out, int out_size) {
    const float* x      = (const float*)d_in[0];
    const int*   batch  = (const int*)  d_in[1];
    const float* in_w1  = (const float*)d_in[2];
    const float* in_b1  = (const float*)d_in[3];
    const float* out_w1 = (const float*)d_in[4];
    const float* out_b1 = (const float*)d_in[5];
    const float* in_w2  = (const float*)d_in[6];
    const float* in_b2  = (const float*)d_in[7];
    const float* out_w2 = (const float*)d_in[8];
    const float* out_b2 = (const float*)d_in[9];
    const float* r_w1   = (const float*)d_in[10];
    const float* r_b1   = (const float*)d_in[11];
    const float* r_w2   = (const float*)d_in[12];
    const float* r_b2   = (const float*)d_in[13];
    const float* r_w3   = (const float*)d_in[14];
    const float* r_b3   = (const float*)d_in[15];
    float* out = (float*)d_out;

    float *qkv, *bufA, *bufB, *pooled, *r1, *r2;
    cudaGetSymbolAddress((void**)&qkv,    g_qkv);
    cudaGetSymbolAddress((void**)&bufA,   g_bufA);
    cudaGetSymbolAddress((void**)&bufB,   g_bufB);
    cudaGetSymbolAddress((void**)&pooled, g_pooled);
    cudaGetSymbolAddress((void**)&r1,     g_r1);
    cudaGetSymbolAddress((void**)&r2,     g_r2);

    cudaFuncSetAttribute(attention_tc_kernel,
                         cudaFuncAttributeMaxDynamicSharedMemorySize, ATTN_SMEM3);
    cudaFuncSetAttribute(mma_gemm_kernel,
                         cudaFuncAttributeMaxDynamicSharedMemorySize, TCG_SMEM);

    compute_starts_kernel<<<(TOTAL_ATOMS + 255) / 256, 256>>>(batch);

    dim3 gQKV(3 * DMODEL / 128, TOTAL_ATOMS / 128);
    dim3 gOUT(DMODEL / 128,     TOTAL_ATOMS / 128);
    dim3 gATT(NUM_GRAPHS, NHEAD);

    // layer 1
    mma_gemm_kernel<<<gQKV, 256, TCG_SMEM>>>(x,    in_w1,  in_b1,  qkv,  3 * DMODEL);
    attention_tc_kernel<<<gATT, 256, ATTN_SMEM3>>>(qkv, bufA);
    mma_gemm_kernel<<<gOUT, 256, TCG_SMEM>>>(bufA, out_w1, out_b1, bufB, DMODEL);

    // layer 2
    mma_gemm_kernel<<<gQKV, 256, TCG_SMEM>>>(bufB, in_w2,  in_b2,  qkv,  3 * DMODEL);
    attention_tc_kernel<<<gATT, 256, ATTN_SMEM3>>>(qkv, bufA);
    mma_gemm_kernel<<<gOUT, 256, TCG_SMEM>>>(bufA, out_w2, out_b2, bufB, DMODEL);

    // pool + readout MLP
    pool_kernel<<<NUM_GRAPHS, DMODEL>>>(bufB, pooled);

    dim3 gR1(DMODEL / 128, NUM_GRAPHS / 128);
    gemm_tn_kernel<true><<<gR1, 256>>>(pooled, r_w1, r_b1, r1, NUM_GRAPHS, DMODEL, DMODEL);
    dim3 gR2(1, NUM_GRAPHS / 128);
    gemm_tn_kernel<true><<<gR2, 256>>>(r1, r_w2, r_b2, r2, NUM_GRAPHS, 128, DMODEL);
    final_kernel<<<NUM_GRAPHS, 128>>>(r2, r_w3, r_b3, out);
}